// round 5
// baseline (speedup 1.0000x reference)
#include <cuda_runtime.h>
#include <cuda_bf16.h>
#include <cstdint>
#include <math.h>

#define N_NODES 512
#define DSTATE  32
#define MDIM    32
#define HMSG    64
#define NSTEPS  5
#define TIp     16
#define TJp     8
#define ASTR    144  // padded bf16 row stride in bytes (72 bf16)
#define NJG     (N_NODES / TJp)   // 64 j-groups

// Persistent scratch (device globals; no allocation allowed)
__device__ float g_h[N_NODES * DSTATE];
__device__ float g_ub[2][N_NODES * HMSG];   // double-buffered by step parity
__device__ float g_vb[2][N_NODES * HMSG];
__device__ float g_msgsum[N_NODES * MDIM];
__device__ int   g_cnt[NJG];
__device__ __align__(16) uint16_t g_w2bf[64 * 72];  // pre-converted bf16, padded rows
__device__ __align__(16) uint16_t g_w3bf[32 * 72];

__device__ __forceinline__ uint32_t bf2_u32(float lo, float hi) {
    __nv_bfloat162 bb = __floats2bfloat162_rn(lo, hi);
    return *reinterpret_cast<uint32_t*>(&bb);
}
__device__ __forceinline__ uint16_t bf1_u16(float x) {
    __nv_bfloat16 h = __float2bfloat16(x);
    return *reinterpret_cast<uint16_t*>(&h);
}

// m16n8k16 bf16 mma, fp32 accumulate (baseline PTX; HMMA on Blackwell)
__device__ __forceinline__ void mma16816(float* c, const uint32_t* a,
                                         uint32_t b0, uint32_t b1) {
    asm volatile(
        "mma.sync.aligned.m16n8k16.row.col.f32.bf16.bf16.f32 "
        "{%0,%1,%2,%3}, {%4,%5,%6,%7}, {%8,%9}, {%0,%1,%2,%3};"
        : "+f"(c[0]), "+f"(c[1]), "+f"(c[2]), "+f"(c[3])
        : "r"(a[0]), "r"(a[1]), "r"(a[2]), "r"(a[3]), "r"(b0), "r"(b1));
}

#define LDB32(base, r, c) (*(const uint32_t*)((base) + (r) * ASTR + (c) * 2))

// ============================================================================
// prep0: h=0 short-circuit (u=b*wbi, v=b*wbj+b1), zero h/msg/cnt,
//        pre-convert W2/W3 to padded bf16. One launch.
__global__ __launch_bounds__(256) void prep0_kernel(
    const float* __restrict__ b,  const float* __restrict__ W1,
    const float* __restrict__ b1, const float* __restrict__ W2,
    const float* __restrict__ W3) {
    int gt = blockIdx.x * blockDim.x + threadIdx.x;
    int nth = gridDim.x * blockDim.x;   // 8192
    for (int idx = gt; idx < N_NODES * HMSG; idx += nth) {
        int node = idx >> 6, l = idx & 63;
        float bn = b[node];
        g_ub[0][idx] = bn * W1[l * 67 + 65];
        g_vb[0][idx] = bn * W1[l * 67 + 66] + b1[l];
    }
    for (int idx = gt; idx < N_NODES * DSTATE; idx += nth) {
        g_h[idx] = 0.0f;
        g_msgsum[idx] = 0.0f;
    }
    if (gt < NJG) g_cnt[gt] = 0;
    for (int idx = gt; idx < 64 * 64; idx += nth) {
        int k = idx >> 6, c = idx & 63;
        g_w2bf[k * 72 + c] = bf1_u16(W2[idx]);
        if (c >= 56) g_w2bf[k * 72 + c + 8] = 0;  // pad tail
    }
    for (int idx = gt; idx < 32 * 64; idx += nth) {
        int k = idx >> 6, c = idx & 63;
        g_w3bf[k * 72 + c] = bf1_u16(W3[idx]);
        if (c >= 56) g_w3bf[k * 72 + c + 8] = 0;
    }
}

// ============================================================================
// pairs: 16i x 8j tile, two bf16 HMMA GEMMs, msg reduction; the last block of
// each j-group runs the fp32 GRU for its 8 nodes + next-step u/v (prep).
__global__ __launch_bounds__(128) void pairs_kernel(
    const float* __restrict__ J,   const float* __restrict__ W1,
    const float* __restrict__ b2,  const float* __restrict__ b3,
    const float* __restrict__ Wih, const float* __restrict__ Whh,
    const float* __restrict__ bih, const float* __restrict__ bhh,
    const float* __restrict__ bb,  const float* __restrict__ b1,
    int parity) {
    __shared__ __align__(16) uint8_t sA[128 * ASTR];
    __shared__ __align__(16) uint8_t sW2[64 * ASTR];
    __shared__ __align__(16) uint8_t sW3[32 * ASTR];
    __shared__ float sU[TIp * 65];
    __shared__ float sV[TJp * 65];
    __shared__ float sWJ[64], sB2[64], sB3[32];
    // finisher scratch
    __shared__ float fx[8][65];      // [h(0:32), msg(32:64)] ; h overwritten by h_new
    __shared__ float fgi[96][8];
    __shared__ float fgh[96][8];
    __shared__ int   sIsLast;

    int tid = threadIdx.x;
    int w = tid >> 5, l = tid & 31;
    int lr = l >> 2, lc = l & 3;
    int i0 = blockIdx.x * TIp, j0 = blockIdx.y * TJp;
    const float* gu = g_ub[parity];
    const float* gv = g_vb[parity];

    // ---- stage pre-converted bf16 weights (plain uint4 copies) ----
    for (int x = tid; x < 576; x += 128)     // 64*72*2 / 16
        ((uint4*)sW2)[x] = ((const uint4*)g_w2bf)[x];
    for (int x = tid; x < 288; x += 128)
        ((uint4*)sW3)[x] = ((const uint4*)g_w3bf)[x];
    for (int x = tid; x < TIp * 64; x += 128) {
        int r = x >> 6, c = x & 63;
        sU[r * 65 + c] = gu[(i0 + r) * 64 + c];
    }
    for (int x = tid; x < TJp * 64; x += 128) {
        int r = x >> 6, c = x & 63;
        sV[r * 65 + c] = gv[(j0 + r) * 64 + c];
    }
    if (tid < 64) {
        sWJ[tid] = W1[tid * 67 + 64];
        sB2[tid] = b2[tid];
    } else if (tid < 96) {
        sB3[tid - 64] = b3[tid - 64];
    }
    __syncthreads();

    // ---- build A1 row: relu(u+v+J*wJ) -> bf16 ----
    {
        int il = tid & 15, jl = tid >> 4;
        float Jij = J[(i0 + il) * N_NODES + (j0 + jl)];
        const float* u = &sU[il * 65];
        const float* v = &sV[jl * 65];
        uint8_t* row = sA + tid * ASTR;
#pragma unroll
        for (int g = 0; g < 8; g++) {
            uint32_t wv[4];
#pragma unroll
            for (int e = 0; e < 4; e++) {
                int c = g * 8 + e * 2;
                float p0 = fmaxf(fmaf(Jij, sWJ[c], u[c] + v[c]), 0.0f);
                float p1 = fmaxf(fmaf(Jij, sWJ[c + 1], u[c + 1] + v[c + 1]), 0.0f);
                wv[e] = bf2_u32(p0, p1);
            }
            *(uint4*)(row + g * 16) = make_uint4(wv[0], wv[1], wv[2], wv[3]);
        }
    }
    __syncwarp();

    // ---- GEMM1: D1[128x64] = A1 @ W2^T ----
    float acc[2][8][4];
#pragma unroll
    for (int mt = 0; mt < 2; mt++)
#pragma unroll
        for (int nt = 0; nt < 8; nt++)
#pragma unroll
            for (int e = 0; e < 4; e++) acc[mt][nt][e] = 0.0f;
#pragma unroll
    for (int ks = 0; ks < 4; ks++) {
        int k0 = ks * 16;
        uint32_t a[2][4];
#pragma unroll
        for (int mt = 0; mt < 2; mt++) {
            int m = w * 32 + mt * 16 + lr;
            a[mt][0] = LDB32(sA, m,     k0 + lc * 2);
            a[mt][1] = LDB32(sA, m + 8, k0 + lc * 2);
            a[mt][2] = LDB32(sA, m,     k0 + 8 + lc * 2);
            a[mt][3] = LDB32(sA, m + 8, k0 + 8 + lc * 2);
        }
#pragma unroll
        for (int nt = 0; nt < 8; nt++) {
            uint32_t b0 = LDB32(sW2, nt * 8 + lr, k0 + lc * 2);
            uint32_t b1w = LDB32(sW2, nt * 8 + lr, k0 + 8 + lc * 2);
            mma16816(acc[0][nt], a[0], b0, b1w);
            mma16816(acc[1][nt], a[1], b0, b1w);
        }
    }

    // ---- epilogue 1: relu(D1+b2) -> bf16 back into sA ----
#pragma unroll
    for (int mt = 0; mt < 2; mt++) {
        int m = w * 32 + mt * 16 + lr;
#pragma unroll
        for (int nt = 0; nt < 8; nt++) {
            int n = nt * 8 + lc * 2;
            float f0 = fmaxf(acc[mt][nt][0] + sB2[n],     0.0f);
            float f1 = fmaxf(acc[mt][nt][1] + sB2[n + 1], 0.0f);
            float f2 = fmaxf(acc[mt][nt][2] + sB2[n],     0.0f);
            float f3 = fmaxf(acc[mt][nt][3] + sB2[n + 1], 0.0f);
            *(uint32_t*)(sA + m * ASTR + n * 2)       = bf2_u32(f0, f1);
            *(uint32_t*)(sA + (m + 8) * ASTR + n * 2) = bf2_u32(f2, f3);
        }
    }
    __syncwarp();

    // ---- GEMM2: D2[128x32] = A2 @ W3^T ----
    float acc2[2][4][4];
#pragma unroll
    for (int mt = 0; mt < 2; mt++)
#pragma unroll
        for (int nt = 0; nt < 4; nt++)
#pragma unroll
            for (int e = 0; e < 4; e++) acc2[mt][nt][e] = 0.0f;
#pragma unroll
    for (int ks = 0; ks < 4; ks++) {
        int k0 = ks * 16;
        uint32_t a[2][4];
#pragma unroll
        for (int mt = 0; mt < 2; mt++) {
            int m = w * 32 + mt * 16 + lr;
            a[mt][0] = LDB32(sA, m,     k0 + lc * 2);
            a[mt][1] = LDB32(sA, m + 8, k0 + lc * 2);
            a[mt][2] = LDB32(sA, m,     k0 + 8 + lc * 2);
            a[mt][3] = LDB32(sA, m + 8, k0 + 8 + lc * 2);
        }
#pragma unroll
        for (int nt = 0; nt < 4; nt++) {
            uint32_t b0 = LDB32(sW3, nt * 8 + lr, k0 + lc * 2);
            uint32_t b1w = LDB32(sW3, nt * 8 + lr, k0 + 8 + lc * 2);
            mma16816(acc2[0][nt], a[0], b0, b1w);
            mma16816(acc2[1][nt], a[1], b0, b1w);
        }
    }

    // ---- epilogue 2: relu(D2+b3); sum over 16 i-lanes; atomic into msg_sum ----
#pragma unroll
    for (int mt = 0; mt < 2; mt++) {
        int jl = 2 * w + mt;
#pragma unroll
        for (int nt = 0; nt < 4; nt++) {
            int n = nt * 8 + lc * 2;
            float s0 = fmaxf(acc2[mt][nt][0] + sB3[n],     0.0f)
                     + fmaxf(acc2[mt][nt][2] + sB3[n],     0.0f);
            float s1 = fmaxf(acc2[mt][nt][1] + sB3[n + 1], 0.0f)
                     + fmaxf(acc2[mt][nt][3] + sB3[n + 1], 0.0f);
#pragma unroll
            for (int off = 4; off <= 16; off <<= 1) {
                s0 += __shfl_xor_sync(0xffffffffu, s0, off);
                s1 += __shfl_xor_sync(0xffffffffu, s1, off);
            }
            if (l < 4) {
                float* dst = &g_msgsum[(j0 + jl) * MDIM + n];
                atomicAdd(dst, s0);
                atomicAdd(dst + 1, s1);
            }
        }
    }

    // ======== finisher: last block of this j-group runs GRU + next prep ======
    __threadfence();
    __syncthreads();
    if (tid == 0) sIsLast = (atomicAdd(&g_cnt[blockIdx.y], 1) == 31);
    __syncthreads();
    if (!sIsLast) return;
    __threadfence();   // acquire: msg_sum atomics from all 32 blocks visible

    // load x = [h, msg] for 8 nodes; zero msg_sum for next step
    for (int idx = tid; idx < 8 * 32; idx += 128) {
        int n = idx >> 5, d = idx & 31;
        fx[n][d] = g_h[(j0 + n) * 32 + d];
        fx[n][32 + d] = g_msgsum[(j0 + n) * 32 + d];
        g_msgsum[(j0 + n) * 32 + d] = 0.0f;
    }
    __syncthreads();

    // gates: thread t<96 computes gate t for all 8 nodes (fp32)
    if (tid < 96) {
        const float* wr = Wih + tid * 64;
        const float* vr = Whh + tid * 32;
        float ai[8], ah[8];
        float bi = bih[tid], bh = bhh[tid];
#pragma unroll
        for (int n = 0; n < 8; n++) { ai[n] = bi; ah[n] = bh; }
        for (int c = 0; c < 64; c++) {
            float wv = wr[c];
#pragma unroll
            for (int n = 0; n < 8; n++) ai[n] = fmaf(wv, fx[n][c], ai[n]);
        }
        for (int c = 0; c < 32; c++) {
            float wv = vr[c];
#pragma unroll
            for (int n = 0; n < 8; n++) ah[n] = fmaf(wv, fx[n][c], ah[n]);
        }
#pragma unroll
        for (int n = 0; n < 8; n++) { fgi[tid][n] = ai[n]; fgh[tid][n] = ah[n]; }
    }
    __syncthreads();

    // h_new: thread t<32 (dim d) for all 8 nodes; overwrite fx[n][d]
    if (tid < 32) {
        int d = tid;
#pragma unroll
        for (int n = 0; n < 8; n++) {
            float r = 1.0f / (1.0f + expf(-(fgi[d][n] + fgh[d][n])));
            float z = 1.0f / (1.0f + expf(-(fgi[32 + d][n] + fgh[32 + d][n])));
            float ng = tanhf(fgi[64 + d][n] + r * fgh[64 + d][n]);
            float hn = (1.0f - z) * ng + z * fx[n][d];
            fx[n][d] = hn;
            g_h[(j0 + n) * 32 + d] = hn;
        }
    }
    __syncthreads();

    // next-step prep: u = h_new@Wi^T + b*wbi ; v = h_new@Wj^T + b*wbj + b1
    {
        int ll = tid & 63, half = tid >> 6;
        const float* wrow = W1 + ll * 67 + half * 32;
        float wb = W1[ll * 67 + 65 + half];
        float* dst = half ? g_vb[parity ^ 1] : g_ub[parity ^ 1];
        float badd = half ? b1[ll] : 0.0f;
#pragma unroll
        for (int n = 0; n < 8; n++) {
            float acc3 = bb[j0 + n] * wb + badd;
#pragma unroll
            for (int d = 0; d < 32; d++) acc3 = fmaf(wrow[d], fx[n][d], acc3);
            dst[(j0 + n) * 64 + ll] = acc3;
        }
    }
    if (tid == 0) g_cnt[blockIdx.y] = 0;
}

// ============================================================================
// readout: 8 nodes x 64 threads per block.
__global__ __launch_bounds__(512) void readout_kernel(
    const float* __restrict__ rW1, const float* __restrict__ rb1,
    const float* __restrict__ rW2, const float* __restrict__ rb2,
    const float* __restrict__ rW3, const float* __restrict__ rb3,
    float* __restrict__ out) {
    __shared__ float sw1[64 * 33];
    __shared__ float sw2[64 * 65];
    __shared__ float sw3[2 * 64];
    __shared__ float sh[8 * 32];
    __shared__ float sy1[8 * 64];
    __shared__ float sy2[8 * 64];
    int tid = threadIdx.x;
    for (int x = tid; x < 64 * 32; x += 512) {
        int r = x >> 5, c = x & 31;
        sw1[r * 33 + c] = rW1[x];
    }
    for (int x = tid; x < 64 * 64; x += 512) {
        int r = x >> 6, c = x & 63;
        sw2[r * 65 + c] = rW2[x];
    }
    if (tid < 128) sw3[tid] = rW3[tid];
    int nl = tid >> 6, t = tid & 63;
    int node = blockIdx.x * 8 + nl;
    if (t < 32) sh[nl * 32 + t] = g_h[node * 32 + t];
    __syncthreads();
    float a = rb1[t];
    const float* w1 = &sw1[t * 33];
    const float* hr = &sh[nl * 32];
#pragma unroll
    for (int c = 0; c < 32; c++) a = fmaf(w1[c], hr[c], a);
    sy1[nl * 64 + t] = fmaxf(a, 0.0f);
    __syncthreads();
    float c2 = rb2[t];
    const float* w2 = &sw2[t * 65];
    const float* y1 = &sy1[nl * 64];
#pragma unroll
    for (int k = 0; k < 64; k++) c2 = fmaf(w2[k], y1[k], c2);
    sy2[nl * 64 + t] = fmaxf(c2, 0.0f);
    __syncthreads();
    if (t < 2) {
        float e = rb3[t];
        const float* y2 = &sy2[nl * 64];
#pragma unroll
        for (int k = 0; k < 64; k++) e = fmaf(sw3[t * 64 + k], y2[k], e);
        e = fmaxf(e, 0.0f);
        out[node * 2 + t] = 1.0f / (1.0f + expf(-e));
    }
}

// ---------------------------------------------------------------------------
extern "C" void kernel_launch(void* const* d_in, const int* in_sizes, int n_in,
                              void* d_out, int out_size) {
    const float* J   = (const float*)d_in[0];
    const float* b   = (const float*)d_in[1];
    const float* W1  = (const float*)d_in[2];
    const float* b1  = (const float*)d_in[3];
    const float* W2  = (const float*)d_in[4];
    const float* b2  = (const float*)d_in[5];
    const float* W3  = (const float*)d_in[6];
    const float* b3  = (const float*)d_in[7];
    const float* Wih = (const float*)d_in[8];
    const float* Whh = (const float*)d_in[9];
    const float* bih = (const float*)d_in[10];
    const float* bhh = (const float*)d_in[11];
    const float* rW1 = (const float*)d_in[12];
    const float* rb1 = (const float*)d_in[13];
    const float* rW2 = (const float*)d_in[14];
    const float* rb2 = (const float*)d_in[15];
    const float* rW3 = (const float*)d_in[16];
    const float* rb3 = (const float*)d_in[17];
    float* out = (float*)d_out;

    prep0_kernel<<<32, 256>>>(b, W1, b1, W2, W3);
    dim3 grid(N_NODES / TIp, N_NODES / TJp);
    for (int s = 0; s < NSTEPS; s++) {
        pairs_kernel<<<grid, 128>>>(J, W1, b2, b3, Wih, Whh, bih, bhh, b, b1, s & 1);
    }
    readout_kernel<<<N_NODES / 8, 512>>>(rW1, rb1, rW2, rb2, rW3, rb3, out);
}